// round 4
// baseline (speedup 1.0000x reference)
#include <cuda_runtime.h>
#include <cuda_bf16.h>
#include <stdint.h>

// T=10, C=3, H=512, W=512, PT=2, PS=7
#define PS 7
#define PT 2
#define CCH 3
#define HH 512
#define WW 512
#define HW (HH * WW)
#define ROWS_PER_Q (PT * CCH * PS)  // 42
#define QCAP 262144

__device__ int g_bins[4 * QCAP];
__device__ int g_counts[4];

__device__ __forceinline__ void red1(float* p, float v) {
    asm volatile("red.global.add.f32 [%0], %1;" :: "l"(p), "f"(v) : "memory");
}
__device__ __forceinline__ void red2(float* p, float a, float b) {
    asm volatile("red.global.add.v2.f32 [%0], {%1,%2};" :: "l"(p), "f"(a), "f"(b) : "memory");
}
__device__ __forceinline__ void red4(float* p, float a, float b, float c, float d) {
    asm volatile("red.global.add.v4.f32 [%0], {%1,%2,%3,%4};"
                 :: "l"(p), "f"(a), "f"(b), "f"(c), "f"(d) : "memory");
}

// ---------------- K1: bin queries by w&3 ----------------
__global__ void __launch_bounds__(256)
bin_kernel(const int* __restrict__ qinds, int Q)
{
    __shared__ int s_cnt[4];
    __shared__ int s_base[4];
    if (threadIdx.x < 4) s_cnt[threadIdx.x] = 0;
    __syncthreads();

    int q = blockIdx.x * blockDim.x + threadIdx.x;
    int a = 0, slot = 0;
    if (q < Q) {
        int w = __ldg(&qinds[3 * q + 2]);
        a = w & 3;
        slot = atomicAdd(&s_cnt[a], 1);
    }
    __syncthreads();
    if (threadIdx.x < 4)
        s_base[threadIdx.x] = atomicAdd(&g_counts[threadIdx.x], s_cnt[threadIdx.x]);
    __syncthreads();
    if (q < Q)
        g_bins[a * QCAP + s_base[a] + slot] = q;
}

// ---------------- K2: alignment-uniform scatter ----------------
__global__ void __launch_bounds__(256)
scatter_binned_kernel(const float* __restrict__ patches,
                      const int*   __restrict__ qinds,
                      float*       __restrict__ out,
                      int nRows, int nTotal)
{
    int r = blockIdx.x * blockDim.x + threadIdx.x;
    if (r >= nRows) return;

    int c0 = __ldg(&g_counts[0]);
    int c1 = __ldg(&g_counts[1]);
    int c2 = __ldg(&g_counts[2]);
    int n0 = c0 * ROWS_PER_Q;
    int n1 = n0 + c1 * ROWS_PER_Q;
    int n2 = n1 + c2 * ROWS_PER_Q;

    int bin, local;
    if      (r < n0) { bin = 0; local = r; }
    else if (r < n1) { bin = 1; local = r - n0; }
    else if (r < n2) { bin = 2; local = r - n1; }
    else             { bin = 3; local = r - n2; }

    int qi  = local / ROWS_PER_Q;
    int rem = local - qi * ROWS_PER_Q;        // 0..41
    int q   = __ldg(&g_bins[bin * QCAP + qi]);

    int dt   = rem / (CCH * PS);
    int rem2 = rem - dt * (CCH * PS);
    int c    = rem2 / PS;
    int di   = rem2 - c * PS;

    int t = __ldg(&qinds[3 * q + 0]);
    int h = __ldg(&qinds[3 * q + 1]);
    int w = __ldg(&qinds[3 * q + 2]);

    int base = ((t + dt) * CCH + c) * HW + (h + di) * WW + w;
    const float* src = patches + (long long)q * (ROWS_PER_Q * PS)
                               + (long long)rem * PS;

    float v[PS];
#pragma unroll
    for (int j = 0; j < PS; ++j) v[j] = __ldg(&src[j]);

    float* p = out + base;

    switch (bin) {  // bin == base & 3, warp-uniform except at bin boundaries
    case 0:
        if (base + 8 <= nTotal) {
            red4(p + 0, v[0], v[1], v[2], v[3]);
            red4(p + 4, v[4], v[5], v[6], 0.0f);
        } else {
            red4(p + 0, v[0], v[1], v[2], v[3]);
            red2(p + 4, v[4], v[5]);
            red1(p + 6, v[6]);
        }
        break;
    case 1:
        red4(p - 1, 0.0f, v[0], v[1], v[2]);
        red4(p + 3, v[3], v[4], v[5], v[6]);
        break;
    case 2:
        red2(p + 0, v[0], v[1]);
        red4(p + 2, v[2], v[3], v[4], v[5]);
        red1(p + 6, v[6]);
        break;
    default:
        red1(p + 0, v[0]);
        red4(p + 1, v[1], v[2], v[3], v[4]);
        red2(p + 5, v[5], v[6]);
        break;
    }
}

// ---------------- fallback (divergent, any Q) ----------------
__global__ void __launch_bounds__(256)
scatter_fallback_kernel(const float* __restrict__ patches,
                        const int*   __restrict__ qinds,
                        float*       __restrict__ out,
                        int nRows, int nTotal)
{
    int rid = blockIdx.x * blockDim.x + threadIdx.x;
    if (rid >= nRows) return;
    int q = rid / ROWS_PER_Q;
    int rem = rid - q * ROWS_PER_Q;
    int dt = rem / (CCH * PS);
    int rem2 = rem - dt * (CCH * PS);
    int c = rem2 / PS;
    int di = rem2 - c * PS;
    int t = __ldg(&qinds[3 * q + 0]);
    int h = __ldg(&qinds[3 * q + 1]);
    int w = __ldg(&qinds[3 * q + 2]);
    int base = ((t + dt) * CCH + c) * HW + (h + di) * WW + w;
    const float* src = patches + (long long)rid * PS;
    float v[PS];
#pragma unroll
    for (int j = 0; j < PS; ++j) v[j] = __ldg(&src[j]);
    float* p = out + base;
    switch (base & 3) {
    case 0:
        if (base + 8 <= nTotal) {
            red4(p, v[0], v[1], v[2], v[3]); red4(p + 4, v[4], v[5], v[6], 0.0f);
        } else {
            red4(p, v[0], v[1], v[2], v[3]); red2(p + 4, v[4], v[5]); red1(p + 6, v[6]);
        }
        break;
    case 1: red4(p - 1, 0.0f, v[0], v[1], v[2]); red4(p + 3, v[3], v[4], v[5], v[6]); break;
    case 2: red2(p, v[0], v[1]); red4(p + 2, v[2], v[3], v[4], v[5]); red1(p + 6, v[6]); break;
    default: red1(p, v[0]); red4(p + 1, v[1], v[2], v[3], v[4]); red2(p + 5, v[5], v[6]); break;
    }
}

extern "C" void kernel_launch(void* const* d_in, const int* in_sizes, int n_in,
                              void* d_out, int out_size)
{
    const float* vid     = (const float*)d_in[0];
    const float* patches = (const float*)d_in[1];
    const int*   qinds   = (const int*)  d_in[2];
    float*       out     = (float*)d_out;

    int Q = in_sizes[2] / 3;
    int nRows = Q * ROWS_PER_Q;
    int threads = 256;
    int blocks = (nRows + threads - 1) / threads;

    cudaMemcpyAsync(out, vid, (size_t)out_size * sizeof(float),
                    cudaMemcpyDeviceToDevice, 0);

    if (Q <= QCAP) {
        void* cnt_addr = nullptr;
        cudaGetSymbolAddress(&cnt_addr, g_counts);
        cudaMemsetAsync(cnt_addr, 0, 4 * sizeof(int), 0);
        int bblocks = (Q + threads - 1) / threads;
        bin_kernel<<<bblocks, threads, 0, 0>>>(qinds, Q);
        scatter_binned_kernel<<<blocks, threads, 0, 0>>>(patches, qinds, out,
                                                         nRows, out_size);
    } else {
        scatter_fallback_kernel<<<blocks, threads, 0, 0>>>(patches, qinds, out,
                                                           nRows, out_size);
    }
}

// round 5
// speedup vs baseline: 1.0519x; 1.0519x over previous
#include <cuda_runtime.h>
#include <cuda_bf16.h>
#include <stdint.h>

// T=10, C=3, H=512, W=512, PT=2, PS=7
// patches: [Q, PT, C, PS, PS] f32; queryInds: [Q,3] i32 (t,h,w); out: [T,C,H,W] f32

#define PS 7
#define PT 2
#define CCH 3
#define HH 512
#define WW 512
#define HW (HH * WW)
#define ROWS_PER_Q (PT * CCH * PS)  // 42
#define TPB 256
#define FPB (TPB * PS)              // 1792 floats per block

__device__ __forceinline__ void red1(float* p, float v) {
    asm volatile("red.global.add.f32 [%0], %1;" :: "l"(p), "f"(v) : "memory");
}
__device__ __forceinline__ void red2(float* p, float a, float b) {
    asm volatile("red.global.add.v2.f32 [%0], {%1,%2};" :: "l"(p), "f"(a), "f"(b) : "memory");
}
__device__ __forceinline__ void red4(float* p, float a, float b, float c, float d) {
    asm volatile("red.global.add.v4.f32 [%0], {%1,%2,%3,%4};"
                 :: "l"(p), "f"(a), "f"(b), "f"(c), "f"(d) : "memory");
}

__global__ void __launch_bounds__(TPB)
scatter_staged_kernel(const float* __restrict__ patches,
                      const int*   __restrict__ qinds,
                      float*       __restrict__ out,
                      int nRows, int nTotal)
{
    __shared__ float s[FPB];

    // ---- phase 1: coalesced staging of this block's 1792 patch floats ----
    long long f0 = (long long)blockIdx.x * FPB;      // first patch float of block
    long long fTotal = (long long)nRows * PS;

    if (f0 + FPB <= fTotal) {
        // full block: 448 aligned float4 loads (f0*4B is 7168B-multiple -> 16B aligned)
        const float4* src4 = (const float4*)(patches + f0);
#pragma unroll
        for (int k = 0; k < FPB / 4 / TPB; ++k) {     // 448/256 -> iterates 1, then tail below
            int i = threadIdx.x + k * TPB;
            *(float4*)&s[i * 4] = src4[i];
        }
        // remaining 192 float4s
        {
            int i = threadIdx.x + (FPB / 4 / TPB) * TPB;
            if (i < FPB / 4) *(float4*)&s[i * 4] = src4[i];
        }
    } else {
        // tail block: scalar guarded loads
        for (int i = threadIdx.x; i < FPB; i += TPB) {
            long long g = f0 + i;
            s[i] = (g < fTotal) ? patches[g] : 0.0f;
        }
    }
    __syncthreads();

    // ---- phase 2: per-thread row scatter with padded v4 REDs ----
    int rid = blockIdx.x * TPB + threadIdx.x;
    if (rid >= nRows) return;

    int q    = rid / ROWS_PER_Q;
    int rem  = rid - q * ROWS_PER_Q;          // 0..41
    int dt   = rem / (CCH * PS);              // 0..1
    int rem2 = rem - dt * (CCH * PS);         // 0..20
    int c    = rem2 / PS;                     // 0..2
    int di   = rem2 - c * PS;                 // 0..6

    int t = __ldg(&qinds[3 * q + 0]);
    int h = __ldg(&qinds[3 * q + 1]);
    int w = __ldg(&qinds[3 * q + 2]);

    int base = ((t + dt) * CCH + c) * HW + (h + di) * WW + w;

    // read this row's 7 floats from smem (stride 7 vs 32 banks: conflict-free)
    float v[PS];
#pragma unroll
    for (int j = 0; j < PS; ++j) v[j] = s[threadIdx.x * PS + j];

    float* p = out + base;

    switch (base & 3) {
    case 0:
        if (base + 8 <= nTotal) {
            red4(p + 0, v[0], v[1], v[2], v[3]);
            red4(p + 4, v[4], v[5], v[6], 0.0f);
        } else {
            red4(p + 0, v[0], v[1], v[2], v[3]);
            red2(p + 4, v[4], v[5]);
            red1(p + 6, v[6]);
        }
        break;
    case 1:
        red4(p - 1, 0.0f, v[0], v[1], v[2]);
        red4(p + 3, v[3], v[4], v[5], v[6]);
        break;
    case 2:
        red2(p + 0, v[0], v[1]);
        red4(p + 2, v[2], v[3], v[4], v[5]);
        red1(p + 6, v[6]);
        break;
    default: // 3
        red1(p + 0, v[0]);
        red4(p + 1, v[1], v[2], v[3], v[4]);
        red2(p + 5, v[5], v[6]);
        break;
    }
}

extern "C" void kernel_launch(void* const* d_in, const int* in_sizes, int n_in,
                              void* d_out, int out_size)
{
    const float* vid     = (const float*)d_in[0];
    const float* patches = (const float*)d_in[1];
    const int*   qinds   = (const int*)  d_in[2];
    float*       out     = (float*)d_out;

    int Q = in_sizes[2] / 3;
    int nRows = Q * ROWS_PER_Q;

    cudaMemcpyAsync(out, vid, (size_t)out_size * sizeof(float),
                    cudaMemcpyDeviceToDevice, 0);

    int blocks = (nRows + TPB - 1) / TPB;
    scatter_staged_kernel<<<blocks, TPB, 0, 0>>>(patches, qinds, out,
                                                 nRows, out_size);
}

// round 6
// speedup vs baseline: 1.1232x; 1.0678x over previous
#include <cuda_runtime.h>
#include <cuda_bf16.h>
#include <stdint.h>

// T=10, C=3, H=512, W=512, PT=2, PS=7
// patches: [Q, PT, C, PS, PS] f32; queryInds: [Q,3] i32 (t,h,w); out: [T,C,H,W] f32

#define PS 7
#define PT 2
#define CCH 3
#define HH 512
#define WW 512
#define HW (HH * WW)
#define ROWS_PER_Q (PT * CCH * PS)  // 42
#define RPT 4                       // rows per thread (ILP)

__device__ __forceinline__ void red1(float* p, float v) {
    asm volatile("red.global.add.f32 [%0], %1;" :: "l"(p), "f"(v) : "memory");
}
__device__ __forceinline__ void red2(float* p, float a, float b) {
    asm volatile("red.global.add.v2.f32 [%0], {%1,%2};" :: "l"(p), "f"(a), "f"(b) : "memory");
}
__device__ __forceinline__ void red4(float* p, float a, float b, float c, float d) {
    asm volatile("red.global.add.v4.f32 [%0], {%1,%2,%3,%4};"
                 :: "l"(p), "f"(a), "f"(b), "f"(c), "f"(d) : "memory");
}

__device__ __forceinline__ void scatter_row(float* p, int base, int nTotal,
                                            const float v[PS]) {
    switch (base & 3) {
    case 0:
        if (base + 8 <= nTotal) {
            red4(p + 0, v[0], v[1], v[2], v[3]);
            red4(p + 4, v[4], v[5], v[6], 0.0f);
        } else {
            red4(p + 0, v[0], v[1], v[2], v[3]);
            red2(p + 4, v[4], v[5]);
            red1(p + 6, v[6]);
        }
        break;
    case 1:
        red4(p - 1, 0.0f, v[0], v[1], v[2]);
        red4(p + 3, v[3], v[4], v[5], v[6]);
        break;
    case 2:
        red2(p + 0, v[0], v[1]);
        red4(p + 2, v[2], v[3], v[4], v[5]);
        red1(p + 6, v[6]);
        break;
    default: // 3
        red1(p + 0, v[0]);
        red4(p + 1, v[1], v[2], v[3], v[4]);
        red2(p + 5, v[5], v[6]);
        break;
    }
}

__global__ void __launch_bounds__(256)
scatter_ilp_kernel(const float* __restrict__ patches,
                   const int*   __restrict__ qinds,
                   float*       __restrict__ out,
                   int nRows, int nThreads, int nTotal)
{
    int tid = blockIdx.x * blockDim.x + threadIdx.x;
    if (tid >= nThreads) return;

    int   rid[RPT];
    bool  act[RPT];
    float v[RPT][PS];
    int   basev[RPT];

    // ---- issue ALL independent loads first (max MLP) ----
#pragma unroll
    for (int k = 0; k < RPT; ++k) {
        int r = tid + k * nThreads;
        rid[k] = r;
        act[k] = (r < nRows);
        if (act[k]) {
            const float* src = patches + (long long)r * PS;
#pragma unroll
            for (int j = 0; j < PS; ++j) v[k][j] = __ldg(&src[j]);
        }
    }

#pragma unroll
    for (int k = 0; k < RPT; ++k) {
        if (act[k]) {
            int r    = rid[k];
            int q    = r / ROWS_PER_Q;
            int rem  = r - q * ROWS_PER_Q;        // 0..41
            int dt   = rem / (CCH * PS);          // 0..1
            int rem2 = rem - dt * (CCH * PS);     // 0..20
            int c    = rem2 / PS;                 // 0..2
            int di   = rem2 - c * PS;             // 0..6

            int t = __ldg(&qinds[3 * q + 0]);
            int h = __ldg(&qinds[3 * q + 1]);
            int w = __ldg(&qinds[3 * q + 2]);
            basev[k] = ((t + dt) * CCH + c) * HW + (h + di) * WW + w;
        }
    }

    // ---- fire REDs ----
#pragma unroll
    for (int k = 0; k < RPT; ++k) {
        if (act[k]) scatter_row(out + basev[k], basev[k], nTotal, v[k]);
    }
}

extern "C" void kernel_launch(void* const* d_in, const int* in_sizes, int n_in,
                              void* d_out, int out_size)
{
    const float* vid     = (const float*)d_in[0];
    const float* patches = (const float*)d_in[1];
    const int*   qinds   = (const int*)  d_in[2];
    float*       out     = (float*)d_out;

    int Q = in_sizes[2] / 3;
    int nRows = Q * ROWS_PER_Q;
    int nThreads = (nRows + RPT - 1) / RPT;

    cudaMemcpyAsync(out, vid, (size_t)out_size * sizeof(float),
                    cudaMemcpyDeviceToDevice, 0);

    int threads = 256;
    int blocks = (nThreads + threads - 1) / threads;
    scatter_ilp_kernel<<<blocks, threads, 0, 0>>>(patches, qinds, out,
                                                  nRows, nThreads, out_size);
}

// round 7
// speedup vs baseline: 1.1340x; 1.0096x over previous
#include <cuda_runtime.h>
#include <cuda_bf16.h>
#include <stdint.h>

// T=10, C=3, H=512, W=512, PT=2, PS=7
// patches: [Q, PT, C, PS, PS] f32; queryInds: [Q,3] i32 (t,h,w); out: [T,C,H,W] f32

#define PS 7
#define PT 2
#define CCH 3
#define HH 512
#define WW 512
#define HW (HH * WW)
#define ROWS_PER_Q (PT * CCH * PS)  // 42
#define RPT 4                       // rows per thread (consecutive)

__device__ __forceinline__ void red1(float* p, float v) {
    asm volatile("red.global.add.f32 [%0], %1;" :: "l"(p), "f"(v) : "memory");
}
__device__ __forceinline__ void red2(float* p, float a, float b) {
    asm volatile("red.global.add.v2.f32 [%0], {%1,%2};" :: "l"(p), "f"(a), "f"(b) : "memory");
}
__device__ __forceinline__ void red4(float* p, float a, float b, float c, float d) {
    asm volatile("red.global.add.v4.f32 [%0], {%1,%2,%3,%4};"
                 :: "l"(p), "f"(a), "f"(b), "f"(c), "f"(d) : "memory");
}

__device__ __forceinline__ void scatter_row(float* p, int base, int nTotal,
                                            const float* v) {
    switch (base & 3) {
    case 0:
        if (base + 8 <= nTotal) {
            red4(p + 0, v[0], v[1], v[2], v[3]);
            red4(p + 4, v[4], v[5], v[6], 0.0f);
        } else {
            red4(p + 0, v[0], v[1], v[2], v[3]);
            red2(p + 4, v[4], v[5]);
            red1(p + 6, v[6]);
        }
        break;
    case 1:
        red4(p - 1, 0.0f, v[0], v[1], v[2]);
        red4(p + 3, v[3], v[4], v[5], v[6]);
        break;
    case 2:
        red2(p + 0, v[0], v[1]);
        red4(p + 2, v[2], v[3], v[4], v[5]);
        red1(p + 6, v[6]);
        break;
    default: // 3
        red1(p + 0, v[0]);
        red4(p + 1, v[1], v[2], v[3], v[4]);
        red2(p + 5, v[5], v[6]);
        break;
    }
}

__global__ void __launch_bounds__(256)
scatter_vec_ilp_kernel(const float* __restrict__ patches,
                       const int*   __restrict__ qinds,
                       float*       __restrict__ out,
                       int nRows, int nTotal)
{
    int tid = blockIdx.x * blockDim.x + threadIdx.x;
    int r0 = tid * RPT;                    // first of 4 consecutive rows
    if (r0 >= nRows) return;

    float v[RPT * PS];                     // 28 floats

    if (r0 + RPT <= nRows) {
        // 28 contiguous floats at byte offset tid*112 -> 16B aligned: 7x LDG.128
        const float4* src4 = (const float4*)(patches + (long long)r0 * PS);
#pragma unroll
        for (int i = 0; i < (RPT * PS) / 4; ++i) {   // 7 vector loads
            float4 x = __ldg(&src4[i]);
            v[i * 4 + 0] = x.x; v[i * 4 + 1] = x.y;
            v[i * 4 + 2] = x.z; v[i * 4 + 3] = x.w;
        }
    } else {
        // tail: scalar guarded
#pragma unroll
        for (int i = 0; i < RPT * PS; ++i) {
            long long g = (long long)r0 * PS + i;
            v[i] = (g < (long long)nRows * PS) ? __ldg(&patches[g]) : 0.0f;
        }
    }

    // compute bases for the 4 rows
    int basev[RPT];
#pragma unroll
    for (int k = 0; k < RPT; ++k) {
        int r = r0 + k;
        if (r < nRows) {
            int q    = r / ROWS_PER_Q;
            int rem  = r - q * ROWS_PER_Q;        // 0..41
            int dt   = rem / (CCH * PS);          // 0..1
            int rem2 = rem - dt * (CCH * PS);     // 0..20
            int c    = rem2 / PS;                 // 0..2
            int di   = rem2 - c * PS;             // 0..6

            int t = __ldg(&qinds[3 * q + 0]);
            int h = __ldg(&qinds[3 * q + 1]);
            int w = __ldg(&qinds[3 * q + 2]);
            basev[k] = ((t + dt) * CCH + c) * HW + (h + di) * WW + w;
        } else {
            basev[k] = -1;
        }
    }

    // fire REDs
#pragma unroll
    for (int k = 0; k < RPT; ++k) {
        if (basev[k] >= 0)
            scatter_row(out + basev[k], basev[k], nTotal, &v[k * PS]);
    }
}

extern "C" void kernel_launch(void* const* d_in, const int* in_sizes, int n_in,
                              void* d_out, int out_size)
{
    const float* vid     = (const float*)d_in[0];
    const float* patches = (const float*)d_in[1];
    const int*   qinds   = (const int*)  d_in[2];
    float*       out     = (float*)d_out;

    int Q = in_sizes[2] / 3;
    int nRows = Q * ROWS_PER_Q;
    int nThreads = (nRows + RPT - 1) / RPT;

    cudaMemcpyAsync(out, vid, (size_t)out_size * sizeof(float),
                    cudaMemcpyDeviceToDevice, 0);

    int threads = 256;
    int blocks = (nThreads + threads - 1) / threads;
    scatter_vec_ilp_kernel<<<blocks, threads, 0, 0>>>(patches, qinds, out,
                                                      nRows, out_size);
}